// round 1
// baseline (speedup 1.0000x reference)
#include <cuda_runtime.h>
#include <cuda_bf16.h>
#include <cstdint>

// Problem constants
#define NN 50000
#define NE 400000
#define D_IN 1024
#define D_HID 512
#define D_LAT 256

// Scratch (static device arrays — allocation-free per harness rules)
__device__ float g_s[(size_t)NN * D_HID];    // s1 [N,512], later reused as s2 [N,256]
__device__ float g_agg[(size_t)NN * D_HID];  // agg1 -> relu -> h [N,512]

// ---------------------------------------------------------------------------
// Tiled fp32 SGEMM: C[M,N] = A[M,K] @ B[K,N], all row-major.
// BM=BN=128, BK=8, 256 threads, 8x8 per thread, float4 global loads.
// ---------------------------------------------------------------------------
#define BM 128
#define BN 128
#define BK 8
#define TM 8
#define TN 8

__global__ __launch_bounds__(256) void sgemm_k(
    const float* __restrict__ A, const float* __restrict__ B,
    float* __restrict__ C, int M, int N, int K)
{
    __shared__ float As[BK][BM + 4];
    __shared__ float Bs[BK][BN];

    const int tid  = threadIdx.x;
    const int brow = blockIdx.y;
    const int bcol = blockIdx.x;

    const int trow = tid / (BN / TN);  // 0..15
    const int tcol = tid % (BN / TN);  // 0..15

    // A tile load mapping: 128 rows x 8 cols, float4 per thread (2 per row)
    const int aRow  = tid >> 1;          // 0..127
    const int aCol4 = (tid & 1) * 4;     // 0 or 4
    // B tile load mapping: 8 rows x 128 cols, float4 per thread
    const int bRow  = tid >> 5;          // 0..7
    const int bCol4 = (tid & 31) * 4;    // 0..124

    const int gARow = brow * BM + aRow;
    const bool aValid = (gARow < M);
    const float* Aptr = A + (size_t)gARow * K;
    const float* Bptr = B + (size_t)bRow * N + (size_t)bcol * BN + bCol4;

    float acc[TM][TN];
#pragma unroll
    for (int i = 0; i < TM; i++)
#pragma unroll
        for (int j = 0; j < TN; j++) acc[i][j] = 0.0f;

    for (int k0 = 0; k0 < K; k0 += BK) {
        float4 aReg = make_float4(0.f, 0.f, 0.f, 0.f);
        if (aValid) aReg = *reinterpret_cast<const float4*>(Aptr + k0 + aCol4);
        float4 bReg = *reinterpret_cast<const float4*>(Bptr + (size_t)k0 * N);

        As[aCol4 + 0][aRow] = aReg.x;
        As[aCol4 + 1][aRow] = aReg.y;
        As[aCol4 + 2][aRow] = aReg.z;
        As[aCol4 + 3][aRow] = aReg.w;
        *reinterpret_cast<float4*>(&Bs[bRow][bCol4]) = bReg;
        __syncthreads();

#pragma unroll
        for (int k = 0; k < BK; k++) {
            float am[TM], bn[TN];
#pragma unroll
            for (int i = 0; i < TM; i++) am[i] = As[k][trow * TM + i];
#pragma unroll
            for (int j = 0; j < TN; j++) bn[j] = Bs[k][tcol * TN + j];
#pragma unroll
            for (int i = 0; i < TM; i++)
#pragma unroll
                for (int j = 0; j < TN; j++)
                    acc[i][j] = fmaf(am[i], bn[j], acc[i][j]);
        }
        __syncthreads();
    }

    const int cRow0 = brow * BM + trow * TM;
    const int cCol0 = bcol * BN + tcol * TN;
#pragma unroll
    for (int i = 0; i < TM; i++) {
        int r = cRow0 + i;
        if (r < M) {
            float4 v0 = make_float4(acc[i][0], acc[i][1], acc[i][2], acc[i][3]);
            float4 v1 = make_float4(acc[i][4], acc[i][5], acc[i][6], acc[i][7]);
            *reinterpret_cast<float4*>(C + (size_t)r * N + cCol0)     = v0;
            *reinterpret_cast<float4*>(C + (size_t)r * N + cCol0 + 4) = v1;
        }
    }
}

// ---------------------------------------------------------------------------
// out[n, :] = bias[:]  (vectorized broadcast init)
// DV4 = D/4 (power of two), DV4_MASK = DV4-1
// ---------------------------------------------------------------------------
__global__ void init_bias_k(float4* __restrict__ out, const float4* __restrict__ bias,
                            unsigned total_v4, unsigned dv4_mask)
{
    unsigned gid = blockIdx.x * blockDim.x + threadIdx.x;
    if (gid >= total_v4) return;
    out[gid] = bias[gid & dv4_mask];
}

// ---------------------------------------------------------------------------
// Scatter-add: agg[dst[e], :] += s[src[e], :] * w[e]
// One thread per (edge, 4-col chunk). Vector red.global.add.v4.f32.
// DSHIFT = log2(D/4)
// ---------------------------------------------------------------------------
__global__ void scatter_add_k(const float* __restrict__ s,
                              const int* __restrict__ src,
                              const int* __restrict__ dst,
                              const float* __restrict__ w,
                              float* __restrict__ agg,
                              unsigned total, int dshift, int D)
{
    unsigned gid = blockIdx.x * blockDim.x + threadIdx.x;
    if (gid >= total) return;
    const unsigned e  = gid >> dshift;
    const unsigned c4 = (gid & ((1u << dshift) - 1u)) << 2;

    const int s_node = __ldg(&src[e]);
    const int d_node = __ldg(&dst[e]);
    const float ww   = __ldg(&w[e]);

    const float4 v = *reinterpret_cast<const float4*>(s + (size_t)s_node * D + c4);
    float* p = agg + (size_t)d_node * D + c4;
    asm volatile("red.global.add.v4.f32 [%0], {%1, %2, %3, %4};"
                 :: "l"(p), "f"(v.x * ww), "f"(v.y * ww), "f"(v.z * ww), "f"(v.w * ww)
                 : "memory");
}

// ---------------------------------------------------------------------------
// In-place ReLU (vectorized)
// ---------------------------------------------------------------------------
__global__ void relu_k(float4* __restrict__ a, unsigned total_v4)
{
    unsigned gid = blockIdx.x * blockDim.x + threadIdx.x;
    if (gid >= total_v4) return;
    float4 v = a[gid];
    v.x = fmaxf(v.x, 0.f);
    v.y = fmaxf(v.y, 0.f);
    v.z = fmaxf(v.z, 0.f);
    v.w = fmaxf(v.w, 0.f);
    a[gid] = v;
}

// ---------------------------------------------------------------------------
// Launch
// ---------------------------------------------------------------------------
extern "C" void kernel_launch(void* const* d_in, const int* in_sizes, int n_in,
                              void* d_out, int out_size)
{
    const float* x  = (const float*)d_in[0];   // [50000, 1024]
    const int*   ei = (const int*)d_in[1];     // [2, 400000] (src row then dst row)
    const float* ew = (const float*)d_in[2];   // [400000]
    const float* W1 = (const float*)d_in[3];   // [1024, 512]
    const float* b1 = (const float*)d_in[4];   // [512]
    const float* W2 = (const float*)d_in[5];   // [512, 256]
    const float* b2 = (const float*)d_in[6];   // [256]
    float* out = (float*)d_out;                // [50000, 256]

    float *s_buf = nullptr, *agg_buf = nullptr;
    cudaGetSymbolAddress((void**)&s_buf, g_s);
    cudaGetSymbolAddress((void**)&agg_buf, g_agg);

    const int*   src = ei;
    const int*   dst = ei + NE;

    // ---- Layer 1 ----
    {
        dim3 grid(D_HID / BN, (NN + BM - 1) / BM);
        sgemm_k<<<grid, 256>>>(x, W1, s_buf, NN, D_HID, D_IN);
    }
    {
        unsigned total_v4 = (unsigned)NN * (D_HID / 4);
        init_bias_k<<<(total_v4 + 255) / 256, 256>>>(
            (float4*)agg_buf, (const float4*)b1, total_v4, (D_HID / 4) - 1);
    }
    {
        unsigned total = (unsigned)NE * (D_HID / 4);   // 51.2M threads
        scatter_add_k<<<(total + 255) / 256, 256>>>(
            s_buf, src, dst, ew, agg_buf, total, 7 /*log2(128)*/, D_HID);
    }
    {
        unsigned total_v4 = (unsigned)NN * (D_HID / 4);
        relu_k<<<(total_v4 + 255) / 256, 256>>>((float4*)agg_buf, total_v4);
    }

    // ---- Layer 2 ----
    {
        dim3 grid(D_LAT / BN, (NN + BM - 1) / BM);
        sgemm_k<<<grid, 256>>>(agg_buf, W2, s_buf, NN, D_LAT, D_HID);
    }
    {
        unsigned total_v4 = (unsigned)NN * (D_LAT / 4);
        init_bias_k<<<(total_v4 + 255) / 256, 256>>>(
            (float4*)out, (const float4*)b2, total_v4, (D_LAT / 4) - 1);
    }
    {
        unsigned total = (unsigned)NE * (D_LAT / 4);   // 25.6M threads
        scatter_add_k<<<(total + 255) / 256, 256>>>(
            s_buf, src, dst, ew, out, total, 6 /*log2(64)*/, D_LAT);
    }
    {
        unsigned total_v4 = (unsigned)NN * (D_LAT / 4);
        relu_k<<<(total_v4 + 255) / 256, 256>>>((float4*)out, total_v4);
    }
}

// round 3
// speedup vs baseline: 2.1183x; 2.1183x over previous
#include <cuda_runtime.h>
#include <cuda_bf16.h>
#include <cstdint>

// ---------------------------------------------------------------------------
// Problem constants
// ---------------------------------------------------------------------------
#define NN    50000
#define NNP   50048              // padded to multiple of 128
#define NE    400000
#define D_IN  1024
#define D_HID 512
#define D_LAT 256

#define K1 (3 * D_IN)    // 3072  split-bf16 [hi | lo | hi]
#define K2 (3 * D_HID)   // 1536

// ---------------------------------------------------------------------------
// Static device scratch (allocation-free)
// ---------------------------------------------------------------------------
__device__ __align__(128) __nv_bfloat16 g_A1[(size_t)NNP * K1];     // ~308 MB
__device__ __align__(128) __nv_bfloat16 g_B1[(size_t)D_HID * K1];   // 3 MB
__device__ __align__(128) __nv_bfloat16 g_A2[(size_t)NNP * K2];     // ~154 MB
__device__ __align__(128) __nv_bfloat16 g_B2[(size_t)D_LAT * K2];   // 0.8 MB
__device__ __align__(128) float g_s[(size_t)NNP * D_HID];           // GEMM out (padded)
__device__ __align__(128) float g_agg[(size_t)NN * D_HID];          // aggregate

// ---------------------------------------------------------------------------
// Helpers
// ---------------------------------------------------------------------------
__device__ __forceinline__ uint32_t smem_u32(const void* p) {
    uint32_t a;
    asm("{ .reg .u64 t; cvta.to.shared.u64 t, %1; cvt.u32.u64 %0, t; }"
        : "=r"(a) : "l"(p));
    return a;
}
__device__ __forceinline__ void cp16(uint32_t dst, const void* src) {
    asm volatile("cp.async.cg.shared.global.L2::128B [%0], [%1], 16;"
                 :: "r"(dst), "l"(src));
}
#define CP_COMMIT() asm volatile("cp.async.commit_group;" ::: "memory")
#define CP_WAIT1()  asm volatile("cp.async.wait_group 1;" ::: "memory")

__device__ __forceinline__ void ldsm_x4(uint32_t& r0, uint32_t& r1,
                                        uint32_t& r2, uint32_t& r3, uint32_t a) {
    asm volatile("ldmatrix.sync.aligned.m8n8.x4.shared.b16 {%0,%1,%2,%3}, [%4];"
                 : "=r"(r0), "=r"(r1), "=r"(r2), "=r"(r3) : "r"(a));
}
__device__ __forceinline__ void mma16816(float& c0, float& c1, float& c2, float& c3,
                                         uint32_t a0, uint32_t a1, uint32_t a2, uint32_t a3,
                                         uint32_t b0, uint32_t b1) {
    asm volatile("mma.sync.aligned.m16n8k16.row.col.f32.bf16.bf16.f32 "
                 "{%0,%1,%2,%3}, {%4,%5,%6,%7}, {%8,%9}, {%0,%1,%2,%3};"
                 : "+f"(c0), "+f"(c1), "+f"(c2), "+f"(c3)
                 : "r"(a0), "r"(a1), "r"(a2), "r"(a3), "r"(b0), "r"(b1));
}

// ---------------------------------------------------------------------------
// bf16 TN GEMM via mma.sync: C[M,N] = A[M,Kp] @ B[N,Kp]^T (both K-major)
// Tile 128x128, BK=64 (128B swizzled rows), 3-stage cp.async pipeline,
// 8 warps (4m x 2n), warp tile 32x64, fp32 register accumulators.
// M is padded (NNP) so all loads/stores are unconditional.
// ---------------------------------------------------------------------------
#define GBK       64
#define STAGE_B   (128 * 128 * 2)         // A(16KB)+B(16KB) per stage
#define GEMM_SMEM (3 * STAGE_B)           // 98304

__global__ __launch_bounds__(256, 2) void gemm_mma_k(
    const __nv_bfloat16* __restrict__ A, const __nv_bfloat16* __restrict__ B,
    float* __restrict__ C, int Kp, int N)
{
    extern __shared__ char smem[];
    const uint32_t sb = smem_u32(smem);

    const int tid  = threadIdx.x;
    const int wid  = tid >> 5;
    const int lane = tid & 31;
    const int wm = (wid >> 1) * 32;       // warp m offset in tile
    const int wn = (wid & 1) * 64;        // warp n offset in tile
    const int m0 = blockIdx.y * 128;
    const int n0 = blockIdx.x * 128;
    const int KT = Kp / GBK;

    // cp.async mapping: 1024 chunks (16B) per operand tile, 4 per thread
    const int lr0 = tid >> 3;             // row base (0..31), +32*i
    const int lc  = tid & 7;              // chunk col

    const __nv_bfloat16* Ag = A + (size_t)m0 * Kp + lc * 8;
    const __nv_bfloat16* Bg = B + (size_t)n0 * Kp + lc * 8;

    // ldmatrix per-thread row mappings
    const int arow = lane & 15;           // A: row within 16
    const int ach  = lane >> 4;           // A: chunk half
    const int brow = (lane & 7) + ((lane >> 4) << 3);  // B: row within 16
    const int bch  = (lane >> 3) & 1;                  // B: chunk half

    float acc[2][8][4];
#pragma unroll
    for (int i = 0; i < 2; i++)
#pragma unroll
        for (int j = 0; j < 8; j++)
#pragma unroll
            for (int q = 0; q < 4; q++) acc[i][j][q] = 0.0f;

    auto load_stage = [&](int st, int kt) {
        const uint32_t sA = sb + st * STAGE_B;
        const uint32_t sB = sA + 16384;
        const int k0 = kt * GBK;
#pragma unroll
        for (int i = 0; i < 4; i++) {
            const int r = lr0 + 32 * i;
            const uint32_t off = r * 128 + ((lc ^ (r & 7)) << 4);
            cp16(sA + off, Ag + (size_t)r * Kp + k0);
            cp16(sB + off, Bg + (size_t)r * Kp + k0);
        }
    };

    // Prologue: 2 stages in flight
    load_stage(0, 0); CP_COMMIT();
    load_stage(1, 1); CP_COMMIT();

    int st = 0;
    for (int kt = 0; kt < KT; kt++) {
        CP_WAIT1();
        __syncthreads();
        {
            const int nk = kt + 2;
            if (nk < KT) load_stage((st + 2 >= 3) ? st - 1 : st + 2, nk);
            CP_COMMIT();
        }
        const uint32_t sA = sb + st * STAGE_B;
        const uint32_t sB = sA + 16384;
#pragma unroll
        for (int ks = 0; ks < 4; ks++) {
            uint32_t a[2][4];
#pragma unroll
            for (int mf = 0; mf < 2; mf++) {
                const int r = wm + mf * 16 + arow;
                const uint32_t addr = sA + r * 128 + (((2 * ks + ach) ^ (r & 7)) << 4);
                ldsm_x4(a[mf][0], a[mf][1], a[mf][2], a[mf][3], addr);
            }
            uint32_t b[8][2];
#pragma unroll
            for (int j = 0; j < 4; j++) {
                const int r = wn + j * 16 + brow;
                const uint32_t addr = sB + r * 128 + (((2 * ks + bch) ^ (r & 7)) << 4);
                uint32_t r0, r1, r2, r3;
                ldsm_x4(r0, r1, r2, r3, addr);
                b[2 * j][0] = r0; b[2 * j][1] = r1;
                b[2 * j + 1][0] = r2; b[2 * j + 1][1] = r3;
            }
#pragma unroll
            for (int mf = 0; mf < 2; mf++)
#pragma unroll
                for (int nf = 0; nf < 8; nf++)
                    mma16816(acc[mf][nf][0], acc[mf][nf][1],
                             acc[mf][nf][2], acc[mf][nf][3],
                             a[mf][0], a[mf][1], a[mf][2], a[mf][3],
                             b[nf][0], b[nf][1]);
        }
        __syncthreads();
        st = (st == 2) ? 0 : st + 1;
    }

    // Epilogue: unconditional stores (C is padded to NNP rows)
    const int crow = m0 + wm + (lane >> 2);
    const int ccol = n0 + wn + 2 * (lane & 3);
#pragma unroll
    for (int mf = 0; mf < 2; mf++) {
#pragma unroll
        for (int nf = 0; nf < 8; nf++) {
            float* p0 = C + (size_t)(crow + mf * 16) * N + ccol + nf * 8;
            float* p1 = p0 + 8 * N;
            *reinterpret_cast<float2*>(p0) = make_float2(acc[mf][nf][0], acc[mf][nf][1]);
            *reinterpret_cast<float2*>(p1) = make_float2(acc[mf][nf][2], acc[mf][nf][3]);
        }
    }
}

// ---------------------------------------------------------------------------
// Split-bf16 conversion: out[m, 0:K]=hi, [K:2K]=lo, [2K:3K]=hi  (optional ReLU)
// ---------------------------------------------------------------------------
__device__ __forceinline__ uint32_t pack2(__nv_bfloat16 a, __nv_bfloat16 b) {
    __nv_bfloat162 t = __halves2bfloat162(a, b);
    return *reinterpret_cast<uint32_t*>(&t);
}

template <bool RELU>
__global__ void split_a_k(const float4* __restrict__ in, __nv_bfloat16* __restrict__ out,
                          unsigned total4, int Kin)
{
    unsigned g = blockIdx.x * blockDim.x + threadIdx.x;
    if (g >= total4) return;
    const unsigned kin4 = (unsigned)Kin / 4;
    const unsigned m  = g / kin4;
    const unsigned k4 = g - m * kin4;
    float4 v = in[g];
    if (RELU) {
        v.x = fmaxf(v.x, 0.f); v.y = fmaxf(v.y, 0.f);
        v.z = fmaxf(v.z, 0.f); v.w = fmaxf(v.w, 0.f);
    }
    __nv_bfloat16 h0 = __float2bfloat16(v.x), h1 = __float2bfloat16(v.y);
    __nv_bfloat16 h2 = __float2bfloat16(v.z), h3 = __float2bfloat16(v.w);
    __nv_bfloat16 l0 = __float2bfloat16(v.x - __bfloat162float(h0));
    __nv_bfloat16 l1 = __float2bfloat16(v.y - __bfloat162float(h1));
    __nv_bfloat16 l2 = __float2bfloat16(v.z - __bfloat162float(h2));
    __nv_bfloat16 l3 = __float2bfloat16(v.w - __bfloat162float(h3));
    const uint2 hv = make_uint2(pack2(h0, h1), pack2(h2, h3));
    const uint2 lv = make_uint2(pack2(l0, l1), pack2(l2, l3));
    const size_t base = (size_t)m * (3 * (size_t)Kin) + k4 * 4;
    *reinterpret_cast<uint2*>(out + base)           = hv;
    *reinterpret_cast<uint2*>(out + base + Kin)     = lv;
    *reinterpret_cast<uint2*>(out + base + 2 * Kin) = hv;
}

// Weights: W[K,N] row-major -> B'[N,3K] K-major: [hi | hi | lo]
__global__ void split_w_k(const float* __restrict__ W, __nv_bfloat16* __restrict__ B,
                          int K, int N)
{
    int k = blockIdx.x * blockDim.x + threadIdx.x;
    int n = blockIdx.y;
    if (k >= K) return;
    float v = W[(size_t)k * N + n];
    __nv_bfloat16 h = __float2bfloat16(v);
    __nv_bfloat16 l = __float2bfloat16(v - __bfloat162float(h));
    const size_t b = (size_t)n * (3 * (size_t)K);
    B[b + k]         = h;
    B[b + K + k]     = h;
    B[b + 2 * K + k] = l;
}

// ---------------------------------------------------------------------------
// out[n, :] = bias[:]
// ---------------------------------------------------------------------------
__global__ void init_bias_k(float4* __restrict__ out, const float4* __restrict__ bias,
                            unsigned total_v4, unsigned dv4_mask)
{
    unsigned gid = blockIdx.x * blockDim.x + threadIdx.x;
    if (gid >= total_v4) return;
    out[gid] = bias[gid & dv4_mask];
}

// ---------------------------------------------------------------------------
// Scatter-add: agg[dst[e], :] += s[src[e], :] * w[e]   (red.global.add.v4.f32)
// ---------------------------------------------------------------------------
__global__ void scatter_add_k(const float* __restrict__ s,
                              const int* __restrict__ src,
                              const int* __restrict__ dst,
                              const float* __restrict__ w,
                              float* __restrict__ agg,
                              unsigned total, int dshift, int D)
{
    unsigned gid = blockIdx.x * blockDim.x + threadIdx.x;
    if (gid >= total) return;
    const unsigned e  = gid >> dshift;
    const unsigned c4 = (gid & ((1u << dshift) - 1u)) << 2;

    const int s_node = __ldg(&src[e]);
    const int d_node = __ldg(&dst[e]);
    const float ww   = __ldg(&w[e]);

    const float4 v = *reinterpret_cast<const float4*>(s + (size_t)s_node * D + c4);
    float* p = agg + (size_t)d_node * D + c4;
    asm volatile("red.global.add.v4.f32 [%0], {%1, %2, %3, %4};"
                 :: "l"(p), "f"(v.x * ww), "f"(v.y * ww), "f"(v.z * ww), "f"(v.w * ww)
                 : "memory");
}

__global__ void relu_k(float4* __restrict__ a, unsigned total_v4)
{
    unsigned gid = blockIdx.x * blockDim.x + threadIdx.x;
    if (gid >= total_v4) return;
    float4 v = a[gid];
    v.x = fmaxf(v.x, 0.f); v.y = fmaxf(v.y, 0.f);
    v.z = fmaxf(v.z, 0.f); v.w = fmaxf(v.w, 0.f);
    a[gid] = v;
}

// ---------------------------------------------------------------------------
// Launch
// ---------------------------------------------------------------------------
extern "C" void kernel_launch(void* const* d_in, const int* in_sizes, int n_in,
                              void* d_out, int out_size)
{
    const float* x  = (const float*)d_in[0];   // [50000, 1024]
    const int*   ei = (const int*)d_in[1];     // [2, 400000]
    const float* ew = (const float*)d_in[2];   // [400000]
    const float* W1 = (const float*)d_in[3];   // [1024, 512]
    const float* b1 = (const float*)d_in[4];   // [512]
    const float* W2 = (const float*)d_in[5];   // [512, 256]
    const float* b2 = (const float*)d_in[6];   // [256]
    float* out = (float*)d_out;                // [50000, 256]

    static bool attr_set = false;
    if (!attr_set) {
        cudaFuncSetAttribute(gemm_mma_k, cudaFuncAttributeMaxDynamicSharedMemorySize,
                             GEMM_SMEM);
        attr_set = true;
    }

    __nv_bfloat16 *A1, *B1, *A2, *B2;
    float *s_buf, *agg_buf;
    cudaGetSymbolAddress((void**)&A1, g_A1);
    cudaGetSymbolAddress((void**)&B1, g_B1);
    cudaGetSymbolAddress((void**)&A2, g_A2);
    cudaGetSymbolAddress((void**)&B2, g_B2);
    cudaGetSymbolAddress((void**)&s_buf, g_s);
    cudaGetSymbolAddress((void**)&agg_buf, g_agg);

    const int* src = ei;
    const int* dst = ei + NE;
    const int nMt = NNP / 128;   // 391

    // Weight splits (tiny)
    split_w_k<<<dim3((D_IN  + 255) / 256, D_HID), 256>>>(W1, B1, D_IN,  D_HID);
    split_w_k<<<dim3((D_HID + 255) / 256, D_LAT), 256>>>(W2, B2, D_HID, D_LAT);

    // ---- Layer 1 ----
    {
        unsigned total4 = (unsigned)NN * (D_IN / 4);
        split_a_k<false><<<(total4 + 255) / 256, 256>>>((const float4*)x, A1, total4, D_IN);
    }
    gemm_mma_k<<<dim3(D_HID / 128, nMt), 256, GEMM_SMEM>>>(A1, B1, s_buf, K1, D_HID);
    {
        unsigned total_v4 = (unsigned)NN * (D_HID / 4);
        init_bias_k<<<(total_v4 + 255) / 256, 256>>>(
            (float4*)agg_buf, (const float4*)b1, total_v4, (D_HID / 4) - 1);
    }
    {
        unsigned total = (unsigned)NE * (D_HID / 4);
        scatter_add_k<<<(total + 255) / 256, 256>>>(
            s_buf, src, dst, ew, agg_buf, total, 7, D_HID);
    }

    // ---- Layer 2 (ReLU fused into the split) ----
    {
        unsigned total4 = (unsigned)NN * (D_HID / 4);
        split_a_k<true><<<(total4 + 255) / 256, 256>>>((const float4*)agg_buf, A2,
                                                       total4, D_HID);
    }
    gemm_mma_k<<<dim3(D_LAT / 128, nMt), 256, GEMM_SMEM>>>(A2, B2, s_buf, K2, D_LAT);
    {
        unsigned total_v4 = (unsigned)NN * (D_LAT / 4);
        init_bias_k<<<(total_v4 + 255) / 256, 256>>>(
            (float4*)out, (const float4*)b2, total_v4, (D_LAT / 4) - 1);
    }
    {
        unsigned total = (unsigned)NE * (D_LAT / 4);
        scatter_add_k<<<(total + 255) / 256, 256>>>(
            s_buf, src, dst, ew, out, total, 6, D_LAT);
    }
    {
        unsigned total_v4 = (unsigned)NN * (D_LAT / 4);
        relu_k<<<(total_v4 + 255) / 256, 256>>>((float4*)out, total_v4);
    }
}

// round 4
// speedup vs baseline: 3.5724x; 1.6864x over previous
#include <cuda_runtime.h>
#include <cuda_fp16.h>
#include <cstdint>

// ---------------------------------------------------------------------------
// Problem constants
// ---------------------------------------------------------------------------
#define NN    50000
#define NNP   50048              // padded to multiple of 128
#define NE    400000
#define D_IN  1024
#define D_HID 512
#define D_LAT 256

#define K1 (2 * D_IN)    // 2048  split-fp16 [hi | lo]
#define K2 (2 * D_HID)   // 1024

// ---------------------------------------------------------------------------
// Static device scratch (allocation-free)
// ---------------------------------------------------------------------------
__device__ __align__(128) __half g_A1[(size_t)NNP * K1];     // 205 MB
__device__ __align__(128) __half g_B1[(size_t)D_HID * K1];   // 2 MB
__device__ __align__(128) __half g_A2[(size_t)NNP * K2];     // 102 MB
__device__ __align__(128) __half g_B2[(size_t)D_LAT * K2];   // 0.5 MB
__device__ __align__(128) float  g_s[(size_t)NNP * D_HID];   // GEMM out (padded)

// CSR scratch
__device__ int   g_deg[NN];
__device__ int   g_cur[NN];
__device__ int   g_off[NN + 1];
__device__ int   g_esrc[NE];
__device__ float g_ew2[NE];

// ---------------------------------------------------------------------------
// Helpers
// ---------------------------------------------------------------------------
__device__ __forceinline__ uint32_t smem_u32(const void* p) {
    uint32_t a;
    asm("{ .reg .u64 t; cvta.to.shared.u64 t, %1; cvt.u32.u64 %0, t; }"
        : "=r"(a) : "l"(p));
    return a;
}
__device__ __forceinline__ void cp16(uint32_t dst, const void* src) {
    asm volatile("cp.async.cg.shared.global.L2::128B [%0], [%1], 16;"
                 :: "r"(dst), "l"(src));
}
#define CP_COMMIT() asm volatile("cp.async.commit_group;" ::: "memory")
#define CP_WAIT1()  asm volatile("cp.async.wait_group 1;" ::: "memory")

__device__ __forceinline__ void ldsm_x4(uint32_t& r0, uint32_t& r1,
                                        uint32_t& r2, uint32_t& r3, uint32_t a) {
    asm volatile("ldmatrix.sync.aligned.m8n8.x4.shared.b16 {%0,%1,%2,%3}, [%4];"
                 : "=r"(r0), "=r"(r1), "=r"(r2), "=r"(r3) : "r"(a));
}
__device__ __forceinline__ void mma16816(float& c0, float& c1, float& c2, float& c3,
                                         uint32_t a0, uint32_t a1, uint32_t a2, uint32_t a3,
                                         uint32_t b0, uint32_t b1) {
    asm volatile("mma.sync.aligned.m16n8k16.row.col.f32.f16.f16.f32 "
                 "{%0,%1,%2,%3}, {%4,%5,%6,%7}, {%8,%9}, {%0,%1,%2,%3};"
                 : "+f"(c0), "+f"(c1), "+f"(c2), "+f"(c3)
                 : "r"(a0), "r"(a1), "r"(a2), "r"(a3), "r"(b0), "r"(b1));
}

// ---------------------------------------------------------------------------
// fp16 TN GEMM via mma.sync: C[M,N] = A[M,Kp] @ B[N,Kp]^T (both K-major)
// Tile 128x128, BK=64 (128B swizzled rows), 3-stage cp.async pipeline,
// 8 warps (4m x 2n), warp tile 32x64, fp32 register accumulators.
// M is padded (NNP) so all loads/stores are unconditional.
// ---------------------------------------------------------------------------
#define GBK       64
#define STAGE_B   (128 * 128 * 2)
#define GEMM_SMEM (3 * STAGE_B)

__global__ __launch_bounds__(256, 2) void gemm_mma_k(
    const __half* __restrict__ A, const __half* __restrict__ B,
    float* __restrict__ C, int Kp, int N)
{
    extern __shared__ char smem[];
    const uint32_t sb = smem_u32(smem);

    const int tid  = threadIdx.x;
    const int wid  = tid >> 5;
    const int lane = tid & 31;
    const int wm = (wid >> 1) * 32;
    const int wn = (wid & 1) * 64;
    const int m0 = blockIdx.y * 128;
    const int n0 = blockIdx.x * 128;
    const int KT = Kp / GBK;

    const int lr0 = tid >> 3;
    const int lc  = tid & 7;

    const __half* Ag = A + (size_t)m0 * Kp + lc * 8;
    const __half* Bg = B + (size_t)n0 * Kp + lc * 8;

    const int arow = lane & 15;
    const int ach  = lane >> 4;
    const int brow = (lane & 7) + ((lane >> 4) << 3);
    const int bch  = (lane >> 3) & 1;

    float acc[2][8][4];
#pragma unroll
    for (int i = 0; i < 2; i++)
#pragma unroll
        for (int j = 0; j < 8; j++)
#pragma unroll
            for (int q = 0; q < 4; q++) acc[i][j][q] = 0.0f;

    auto load_stage = [&](int st, int kt) {
        const uint32_t sA = sb + st * STAGE_B;
        const uint32_t sB = sA + 16384;
        const int k0 = kt * GBK;
#pragma unroll
        for (int i = 0; i < 4; i++) {
            const int r = lr0 + 32 * i;
            const uint32_t off = r * 128 + ((lc ^ (r & 7)) << 4);
            cp16(sA + off, Ag + (size_t)r * Kp + k0);
            cp16(sB + off, Bg + (size_t)r * Kp + k0);
        }
    };

    load_stage(0, 0); CP_COMMIT();
    load_stage(1, 1); CP_COMMIT();

    int st = 0;
    for (int kt = 0; kt < KT; kt++) {
        CP_WAIT1();
        __syncthreads();
        {
            const int nk = kt + 2;
            if (nk < KT) load_stage((st + 2 >= 3) ? st - 1 : st + 2, nk);
            CP_COMMIT();
        }
        const uint32_t sA = sb + st * STAGE_B;
        const uint32_t sB = sA + 16384;
#pragma unroll
        for (int ks = 0; ks < 4; ks++) {
            uint32_t a[2][4];
#pragma unroll
            for (int mf = 0; mf < 2; mf++) {
                const int r = wm + mf * 16 + arow;
                const uint32_t addr = sA + r * 128 + (((2 * ks + ach) ^ (r & 7)) << 4);
                ldsm_x4(a[mf][0], a[mf][1], a[mf][2], a[mf][3], addr);
            }
            uint32_t b[8][2];
#pragma unroll
            for (int j = 0; j < 4; j++) {
                const int r = wn + j * 16 + brow;
                const uint32_t addr = sB + r * 128 + (((2 * ks + bch) ^ (r & 7)) << 4);
                uint32_t r0, r1, r2, r3;
                ldsm_x4(r0, r1, r2, r3, addr);
                b[2 * j][0] = r0; b[2 * j][1] = r1;
                b[2 * j + 1][0] = r2; b[2 * j + 1][1] = r3;
            }
#pragma unroll
            for (int mf = 0; mf < 2; mf++)
#pragma unroll
                for (int nf = 0; nf < 8; nf++)
                    mma16816(acc[mf][nf][0], acc[mf][nf][1],
                             acc[mf][nf][2], acc[mf][nf][3],
                             a[mf][0], a[mf][1], a[mf][2], a[mf][3],
                             b[nf][0], b[nf][1]);
        }
        __syncthreads();
        st = (st == 2) ? 0 : st + 1;
    }

    const int crow = m0 + wm + (lane >> 2);
    const int ccol = n0 + wn + 2 * (lane & 3);
#pragma unroll
    for (int mf = 0; mf < 2; mf++) {
#pragma unroll
        for (int nf = 0; nf < 8; nf++) {
            float* p0 = C + (size_t)(crow + mf * 16) * N + ccol + nf * 8;
            float* p1 = p0 + 8 * N;
            *reinterpret_cast<float2*>(p0) = make_float2(acc[mf][nf][0], acc[mf][nf][1]);
            *reinterpret_cast<float2*>(p1) = make_float2(acc[mf][nf][2], acc[mf][nf][3]);
        }
    }
}

// ---------------------------------------------------------------------------
// fp16 split helpers
// ---------------------------------------------------------------------------
__device__ __forceinline__ uint32_t packh2(__half a, __half b) {
    __half2 t = __halves2half2(a, b);
    return *reinterpret_cast<uint32_t*>(&t);
}

// x[M,K] fp32 -> A'[M,2K] fp16: [hi | lo]
__global__ void split_a_k(const float4* __restrict__ in, __half* __restrict__ out,
                          unsigned total4, int Kin)
{
    unsigned g = blockIdx.x * blockDim.x + threadIdx.x;
    if (g >= total4) return;
    const unsigned kin4 = (unsigned)Kin / 4;
    const unsigned m  = g / kin4;
    const unsigned k4 = g - m * kin4;
    const float4 v = in[g];
    const __half h0 = __float2half_rn(v.x), h1 = __float2half_rn(v.y);
    const __half h2 = __float2half_rn(v.z), h3 = __float2half_rn(v.w);
    const __half l0 = __float2half_rn(v.x - __half2float(h0));
    const __half l1 = __float2half_rn(v.y - __half2float(h1));
    const __half l2 = __float2half_rn(v.z - __half2float(h2));
    const __half l3 = __float2half_rn(v.w - __half2float(h3));
    const size_t base = (size_t)m * (2 * (size_t)Kin) + k4 * 4;
    *reinterpret_cast<uint2*>(out + base)       = make_uint2(packh2(h0, h1), packh2(h2, h3));
    *reinterpret_cast<uint2*>(out + base + Kin) = make_uint2(packh2(l0, l1), packh2(l2, l3));
}

// W[K,N] row-major -> B'[N,2K] fp16 K-major: [hi | hi]
__global__ void split_w_k(const float* __restrict__ W, __half* __restrict__ B,
                          int K, int N)
{
    int k = blockIdx.x * blockDim.x + threadIdx.x;
    int n = blockIdx.y;
    if (k >= K) return;
    const __half h = __float2half_rn(W[(size_t)k * N + n]);
    const size_t b = (size_t)n * (2 * (size_t)K);
    B[b + k]     = h;
    B[b + K + k] = h;
}

// ---------------------------------------------------------------------------
// CSR build: deg-zero, histogram, 1-block scan, fill
// ---------------------------------------------------------------------------
__global__ void zero_deg_k() {
    int i = blockIdx.x * blockDim.x + threadIdx.x;
    if (i < NN) g_deg[i] = 0;
}
__global__ void hist_k(const int* __restrict__ dst) {
    int e = blockIdx.x * blockDim.x + threadIdx.x;
    if (e < NE) atomicAdd(&g_deg[dst[e]], 1);
}

#define SCAN_T  1024
#define SCAN_CH 49   // 49*1024 = 50176 >= NN
__global__ __launch_bounds__(SCAN_T) void scan_k()
{
    __shared__ int ssum[SCAN_T];
    const int t = threadIdx.x;
    const int base = t * SCAN_CH;
    int loc[SCAN_CH];
    int s = 0;
#pragma unroll
    for (int i = 0; i < SCAN_CH; i++) {
        const int idx = base + i;
        const int v = (idx < NN) ? g_deg[idx] : 0;
        loc[i] = s;
        s += v;
    }
    ssum[t] = s;
    __syncthreads();
    for (int d = 1; d < SCAN_T; d <<= 1) {
        int v = 0;
        if (t >= d) v = ssum[t - d];
        __syncthreads();
        if (t >= d) ssum[t] += v;
        __syncthreads();
    }
    const int excl = (t == 0) ? 0 : ssum[t - 1];
#pragma unroll
    for (int i = 0; i < SCAN_CH; i++) {
        const int idx = base + i;
        if (idx < NN) {
            const int o = excl + loc[i];
            g_off[idx] = o;
            g_cur[idx] = o;
        }
    }
    if (t == 0) g_off[NN] = NE;
}

__global__ void fill_k(const int* __restrict__ src, const int* __restrict__ dst,
                       const float* __restrict__ w)
{
    int e = blockIdx.x * blockDim.x + threadIdx.x;
    if (e >= NE) return;
    const int d = dst[e];
    const int p = atomicAdd(&g_cur[d], 1);
    g_esrc[p] = src[e];
    g_ew2[p]  = w[e];
}

// ---------------------------------------------------------------------------
// Fused aggregation 1: h = relu(segsum(s[src]*w) + b1); emit fp16 [hi|lo] -> A2
// One block (128 thr) per node; thread t owns cols [4t, 4t+4).
// ---------------------------------------------------------------------------
__global__ __launch_bounds__(128) void agg1_k(const float* __restrict__ s,
                                              const float* __restrict__ b1,
                                              __half* __restrict__ A2)
{
    const int n = blockIdx.x;
    const int t = threadIdx.x;
    const int beg = __ldg(&g_off[n]);
    const int end = __ldg(&g_off[n + 1]);

    float4 acc = __ldg(reinterpret_cast<const float4*>(b1) + t);
    for (int j = beg; j < end; j++) {
        const int   sr = __ldg(&g_esrc[j]);
        const float w  = __ldg(&g_ew2[j]);
        const float4 v = __ldg(reinterpret_cast<const float4*>(s + (size_t)sr * D_HID) + t);
        acc.x = fmaf(w, v.x, acc.x);
        acc.y = fmaf(w, v.y, acc.y);
        acc.z = fmaf(w, v.z, acc.z);
        acc.w = fmaf(w, v.w, acc.w);
    }
    acc.x = fmaxf(acc.x, 0.f); acc.y = fmaxf(acc.y, 0.f);
    acc.z = fmaxf(acc.z, 0.f); acc.w = fmaxf(acc.w, 0.f);

    const __half h0 = __float2half_rn(acc.x), h1 = __float2half_rn(acc.y);
    const __half h2 = __float2half_rn(acc.z), h3 = __float2half_rn(acc.w);
    const __half l0 = __float2half_rn(acc.x - __half2float(h0));
    const __half l1 = __float2half_rn(acc.y - __half2float(h1));
    const __half l2 = __float2half_rn(acc.z - __half2float(h2));
    const __half l3 = __float2half_rn(acc.w - __half2float(h3));

    __half* row = A2 + (size_t)n * K2;
    reinterpret_cast<uint2*>(row)[t]         = make_uint2(packh2(h0, h1), packh2(h2, h3));
    reinterpret_cast<uint2*>(row + D_HID)[t] = make_uint2(packh2(l0, l1), packh2(l2, l3));
}

// ---------------------------------------------------------------------------
// Fused aggregation 2: out = relu(segsum(s2[src]*w) + b2)
// One block (64 thr) per node; thread t owns cols [4t, 4t+4).
// ---------------------------------------------------------------------------
__global__ __launch_bounds__(64) void agg2_k(const float* __restrict__ s2,
                                             const float* __restrict__ b2,
                                             float* __restrict__ out)
{
    const int n = blockIdx.x;
    const int t = threadIdx.x;
    const int beg = __ldg(&g_off[n]);
    const int end = __ldg(&g_off[n + 1]);

    float4 acc = __ldg(reinterpret_cast<const float4*>(b2) + t);
    for (int j = beg; j < end; j++) {
        const int   sr = __ldg(&g_esrc[j]);
        const float w  = __ldg(&g_ew2[j]);
        const float4 v = __ldg(reinterpret_cast<const float4*>(s2 + (size_t)sr * D_LAT) + t);
        acc.x = fmaf(w, v.x, acc.x);
        acc.y = fmaf(w, v.y, acc.y);
        acc.z = fmaf(w, v.z, acc.z);
        acc.w = fmaf(w, v.w, acc.w);
    }
    acc.x = fmaxf(acc.x, 0.f); acc.y = fmaxf(acc.y, 0.f);
    acc.z = fmaxf(acc.z, 0.f); acc.w = fmaxf(acc.w, 0.f);
    reinterpret_cast<float4*>(out + (size_t)n * D_LAT)[t] = acc;
}

// ---------------------------------------------------------------------------
// Launch
// ---------------------------------------------------------------------------
extern "C" void kernel_launch(void* const* d_in, const int* in_sizes, int n_in,
                              void* d_out, int out_size)
{
    const float* x  = (const float*)d_in[0];   // [50000, 1024]
    const int*   ei = (const int*)d_in[1];     // [2, 400000]
    const float* ew = (const float*)d_in[2];   // [400000]
    const float* W1 = (const float*)d_in[3];   // [1024, 512]
    const float* b1 = (const float*)d_in[4];   // [512]
    const float* W2 = (const float*)d_in[5];   // [512, 256]
    const float* b2 = (const float*)d_in[6];   // [256]
    float* out = (float*)d_out;                // [50000, 256]

    static bool attr_set = false;
    if (!attr_set) {
        cudaFuncSetAttribute(gemm_mma_k, cudaFuncAttributeMaxDynamicSharedMemorySize,
                             GEMM_SMEM);
        attr_set = true;
    }

    __half *A1, *B1, *A2, *B2;
    float *s_buf;
    cudaGetSymbolAddress((void**)&A1, g_A1);
    cudaGetSymbolAddress((void**)&B1, g_B1);
    cudaGetSymbolAddress((void**)&A2, g_A2);
    cudaGetSymbolAddress((void**)&B2, g_B2);
    cudaGetSymbolAddress((void**)&s_buf, g_s);

    const int* src = ei;
    const int* dst = ei + NE;
    const int nMt = NNP / 128;   // 391

    // Weight splits (tiny)
    split_w_k<<<dim3((D_IN  + 255) / 256, D_HID), 256>>>(W1, B1, D_IN,  D_HID);
    split_w_k<<<dim3((D_HID + 255) / 256, D_LAT), 256>>>(W2, B2, D_HID, D_LAT);

    // Input split
    {
        unsigned total4 = (unsigned)NN * (D_IN / 4);
        split_a_k<<<(total4 + 255) / 256, 256>>>((const float4*)x, A1, total4, D_IN);
    }

    // CSR build
    zero_deg_k<<<(NN + 255) / 256, 256>>>();
    hist_k<<<(NE + 255) / 256, 256>>>(dst);
    scan_k<<<1, SCAN_T>>>();
    fill_k<<<(NE + 255) / 256, 256>>>(src, dst, ew);

    // ---- Layer 1 ----
    gemm_mma_k<<<dim3(D_HID / 128, nMt), 256, GEMM_SMEM>>>(A1, B1, s_buf, K1, D_HID);
    agg1_k<<<NN, 128>>>(s_buf, b1, A2);   // fused: agg + b1 + relu + fp16 split

    // ---- Layer 2 ----
    gemm_mma_k<<<dim3(D_LAT / 128, nMt), 256, GEMM_SMEM>>>(A2, B2, s_buf, K2, D_LAT);
    agg2_k<<<NN, 64>>>(s_buf, b2, out);   // fused: agg + b2 + relu
}

// round 5
// speedup vs baseline: 5.2386x; 1.4664x over previous
#include <cuda_runtime.h>
#include <cuda_fp16.h>
#include <cstdint>

// ---------------------------------------------------------------------------
// Problem constants
// ---------------------------------------------------------------------------
#define NN    50000
#define NNP   50048              // padded to multiple of 128
#define NE    400000
#define D_IN  1024
#define D_HID 512
#define D_LAT 256

#define K1 D_IN    // 1024  plain fp16
#define K2 D_HID   // 512

// ---------------------------------------------------------------------------
// Static device scratch (allocation-free)
// ---------------------------------------------------------------------------
__device__ __align__(128) __half g_A1[(size_t)NNP * K1];     // 102 MB
__device__ __align__(128) __half g_B1[(size_t)D_HID * K1];   // 1 MB
__device__ __align__(128) __half g_A2[(size_t)NNP * K2];     // 51 MB
__device__ __align__(128) __half g_B2[(size_t)D_LAT * K2];   // 0.25 MB
__device__ __align__(128) __half g_s[(size_t)NNP * D_HID];   // GEMM out, fp16

// CSR scratch
__device__ int   g_deg[NN];
__device__ int   g_cur[NN];
__device__ int   g_off[NN + 1];
__device__ int   g_esrc[NE];
__device__ float g_ew2[NE];

// ---------------------------------------------------------------------------
// Helpers
// ---------------------------------------------------------------------------
__device__ __forceinline__ uint32_t smem_u32(const void* p) {
    uint32_t a;
    asm("{ .reg .u64 t; cvta.to.shared.u64 t, %1; cvt.u32.u64 %0, t; }"
        : "=r"(a) : "l"(p));
    return a;
}
__device__ __forceinline__ void cp16(uint32_t dst, const void* src) {
    asm volatile("cp.async.cg.shared.global.L2::128B [%0], [%1], 16;"
                 :: "r"(dst), "l"(src));
}
#define CP_COMMIT() asm volatile("cp.async.commit_group;" ::: "memory")
#define CP_WAIT1()  asm volatile("cp.async.wait_group 1;" ::: "memory")

__device__ __forceinline__ void ldsm_x4(uint32_t& r0, uint32_t& r1,
                                        uint32_t& r2, uint32_t& r3, uint32_t a) {
    asm volatile("ldmatrix.sync.aligned.m8n8.x4.shared.b16 {%0,%1,%2,%3}, [%4];"
                 : "=r"(r0), "=r"(r1), "=r"(r2), "=r"(r3) : "r"(a));
}
__device__ __forceinline__ void mma16816(float& c0, float& c1, float& c2, float& c3,
                                         uint32_t a0, uint32_t a1, uint32_t a2, uint32_t a3,
                                         uint32_t b0, uint32_t b1) {
    asm volatile("mma.sync.aligned.m16n8k16.row.col.f32.f16.f16.f32 "
                 "{%0,%1,%2,%3}, {%4,%5,%6,%7}, {%8,%9}, {%0,%1,%2,%3};"
                 : "+f"(c0), "+f"(c1), "+f"(c2), "+f"(c3)
                 : "r"(a0), "r"(a1), "r"(a2), "r"(a3), "r"(b0), "r"(b1));
}

// ---------------------------------------------------------------------------
// fp16 TN GEMM via mma.sync: C[M,N] = A[M,Kp] @ B[N,Kp]^T (both K-major),
// C written in fp16. Tile 128x128, BK=64 (swizzled), 3-stage cp.async
// pipeline, 8 warps (4m x 2n), fp32 register accumulators.
// ---------------------------------------------------------------------------
#define GBK       64
#define STAGE_B   (128 * 128 * 2)
#define GEMM_SMEM (3 * STAGE_B)

__global__ __launch_bounds__(256, 2) void gemm_mma_k(
    const __half* __restrict__ A, const __half* __restrict__ B,
    __half* __restrict__ C, int Kp, int N)
{
    extern __shared__ char smem[];
    const uint32_t sb = smem_u32(smem);

    const int tid  = threadIdx.x;
    const int wid  = tid >> 5;
    const int lane = tid & 31;
    const int wm = (wid >> 1) * 32;
    const int wn = (wid & 1) * 64;
    const int m0 = blockIdx.y * 128;
    const int n0 = blockIdx.x * 128;
    const int KT = Kp / GBK;

    const int lr0 = tid >> 3;
    const int lc  = tid & 7;

    const __half* Ag = A + (size_t)m0 * Kp + lc * 8;
    const __half* Bg = B + (size_t)n0 * Kp + lc * 8;

    const int arow = lane & 15;
    const int ach  = lane >> 4;
    const int brow = (lane & 7) + ((lane >> 4) << 3);
    const int bch  = (lane >> 3) & 1;

    float acc[2][8][4];
#pragma unroll
    for (int i = 0; i < 2; i++)
#pragma unroll
        for (int j = 0; j < 8; j++)
#pragma unroll
            for (int q = 0; q < 4; q++) acc[i][j][q] = 0.0f;

    auto load_stage = [&](int st, int kt) {
        const uint32_t sA = sb + st * STAGE_B;
        const uint32_t sB = sA + 16384;
        const int k0 = kt * GBK;
#pragma unroll
        for (int i = 0; i < 4; i++) {
            const int r = lr0 + 32 * i;
            const uint32_t off = r * 128 + ((lc ^ (r & 7)) << 4);
            cp16(sA + off, Ag + (size_t)r * Kp + k0);
            cp16(sB + off, Bg + (size_t)r * Kp + k0);
        }
    };

    load_stage(0, 0); CP_COMMIT();
    load_stage(1, 1); CP_COMMIT();

    int st = 0;
    for (int kt = 0; kt < KT; kt++) {
        CP_WAIT1();
        __syncthreads();
        {
            const int nk = kt + 2;
            if (nk < KT) load_stage((st + 2 >= 3) ? st - 1 : st + 2, nk);
            CP_COMMIT();
        }
        const uint32_t sA = sb + st * STAGE_B;
        const uint32_t sB = sA + 16384;
#pragma unroll
        for (int ks = 0; ks < 4; ks++) {
            uint32_t a[2][4];
#pragma unroll
            for (int mf = 0; mf < 2; mf++) {
                const int r = wm + mf * 16 + arow;
                const uint32_t addr = sA + r * 128 + (((2 * ks + ach) ^ (r & 7)) << 4);
                ldsm_x4(a[mf][0], a[mf][1], a[mf][2], a[mf][3], addr);
            }
            uint32_t b[8][2];
#pragma unroll
            for (int j = 0; j < 4; j++) {
                const int r = wn + j * 16 + brow;
                const uint32_t addr = sB + r * 128 + (((2 * ks + bch) ^ (r & 7)) << 4);
                uint32_t r0, r1, r2, r3;
                ldsm_x4(r0, r1, r2, r3, addr);
                b[2 * j][0] = r0; b[2 * j][1] = r1;
                b[2 * j + 1][0] = r2; b[2 * j + 1][1] = r3;
            }
#pragma unroll
            for (int mf = 0; mf < 2; mf++)
#pragma unroll
                for (int nf = 0; nf < 8; nf++)
                    mma16816(acc[mf][nf][0], acc[mf][nf][1],
                             acc[mf][nf][2], acc[mf][nf][3],
                             a[mf][0], a[mf][1], a[mf][2], a[mf][3],
                             b[nf][0], b[nf][1]);
        }
        __syncthreads();
        st = (st == 2) ? 0 : st + 1;
    }

    // Epilogue: fp16 stores (C padded to NNP rows -> unconditional)
    const int crow = m0 + wm + (lane >> 2);
    const int ccol = n0 + wn + 2 * (lane & 3);
#pragma unroll
    for (int mf = 0; mf < 2; mf++) {
#pragma unroll
        for (int nf = 0; nf < 8; nf++) {
            __half* p0 = C + (size_t)(crow + mf * 16) * N + ccol + nf * 8;
            __half* p1 = p0 + 8 * N;
            *reinterpret_cast<__half2*>(p0) =
                __floats2half2_rn(acc[mf][nf][0], acc[mf][nf][1]);
            *reinterpret_cast<__half2*>(p1) =
                __floats2half2_rn(acc[mf][nf][2], acc[mf][nf][3]);
        }
    }
}

// ---------------------------------------------------------------------------
// x[M,K] fp32 -> A1[M,K] fp16
// ---------------------------------------------------------------------------
__global__ void split_a_k(const float4* __restrict__ in, __half* __restrict__ out,
                          unsigned total4)
{
    unsigned g = blockIdx.x * blockDim.x + threadIdx.x;
    if (g >= total4) return;
    const float4 v = in[g];
    const __half2 p0 = __floats2half2_rn(v.x, v.y);
    const __half2 p1 = __floats2half2_rn(v.z, v.w);
    reinterpret_cast<uint2*>(out)[g] =
        make_uint2(*reinterpret_cast<const uint32_t*>(&p0),
                   *reinterpret_cast<const uint32_t*>(&p1));
}

// W[K,N] row-major -> B[N,K] fp16 K-major (transpose + convert)
__global__ void split_w_k(const float* __restrict__ W, __half* __restrict__ B,
                          int K, int N)
{
    int k = blockIdx.x * blockDim.x + threadIdx.x;
    int n = blockIdx.y;
    if (k >= K) return;
    B[(size_t)n * K + k] = __float2half_rn(W[(size_t)k * N + n]);
}

// ---------------------------------------------------------------------------
// CSR build: deg-zero, histogram, 1-block scan, fill
// ---------------------------------------------------------------------------
__global__ void zero_deg_k() {
    int i = blockIdx.x * blockDim.x + threadIdx.x;
    if (i < NN) g_deg[i] = 0;
}
__global__ void hist_k(const int* __restrict__ dst) {
    int e = blockIdx.x * blockDim.x + threadIdx.x;
    if (e < NE) atomicAdd(&g_deg[dst[e]], 1);
}

#define SCAN_T  1024
#define SCAN_CH 49   // 49*1024 = 50176 >= NN
__global__ __launch_bounds__(SCAN_T) void scan_k()
{
    __shared__ int ssum[SCAN_T];
    const int t = threadIdx.x;
    const int base = t * SCAN_CH;
    int loc[SCAN_CH];
    int s = 0;
#pragma unroll
    for (int i = 0; i < SCAN_CH; i++) {
        const int idx = base + i;
        const int v = (idx < NN) ? g_deg[idx] : 0;
        loc[i] = s;
        s += v;
    }
    ssum[t] = s;
    __syncthreads();
    for (int d = 1; d < SCAN_T; d <<= 1) {
        int v = 0;
        if (t >= d) v = ssum[t - d];
        __syncthreads();
        if (t >= d) ssum[t] += v;
        __syncthreads();
    }
    const int excl = (t == 0) ? 0 : ssum[t - 1];
#pragma unroll
    for (int i = 0; i < SCAN_CH; i++) {
        const int idx = base + i;
        if (idx < NN) {
            const int o = excl + loc[i];
            g_off[idx] = o;
            g_cur[idx] = o;
        }
    }
    if (t == 0) g_off[NN] = NE;
}

__global__ void fill_k(const int* __restrict__ src, const int* __restrict__ dst,
                       const float* __restrict__ w)
{
    int e = blockIdx.x * blockDim.x + threadIdx.x;
    if (e >= NE) return;
    const int d = dst[e];
    const int p = atomicAdd(&g_cur[d], 1);
    g_esrc[p] = src[e];
    g_ew2[p]  = w[e];
}

// ---------------------------------------------------------------------------
// Fused aggregation 1: h = relu(segsum(s[src]*w) + b1) -> fp16 A2.
// One block (128 thr) per node; thread t owns cols [4t, 4t+4). s is fp16.
// ---------------------------------------------------------------------------
__global__ __launch_bounds__(128) void agg1_k(const __half* __restrict__ s,
                                              const float* __restrict__ b1,
                                              __half* __restrict__ A2)
{
    const int n = blockIdx.x;
    const int t = threadIdx.x;
    const int beg = __ldg(&g_off[n]);
    const int end = __ldg(&g_off[n + 1]);

    float4 acc = __ldg(reinterpret_cast<const float4*>(b1) + t);
    for (int j = beg; j < end; j++) {
        const int   sr = __ldg(&g_esrc[j]);
        const float w  = __ldg(&g_ew2[j]);
        const uint2 pv = __ldg(reinterpret_cast<const uint2*>(s + (size_t)sr * D_HID) + t);
        const __half2 h0 = *reinterpret_cast<const __half2*>(&pv.x);
        const __half2 h1 = *reinterpret_cast<const __half2*>(&pv.y);
        const float2 f0 = __half22float2(h0);
        const float2 f1 = __half22float2(h1);
        acc.x = fmaf(w, f0.x, acc.x);
        acc.y = fmaf(w, f0.y, acc.y);
        acc.z = fmaf(w, f1.x, acc.z);
        acc.w = fmaf(w, f1.y, acc.w);
    }
    acc.x = fmaxf(acc.x, 0.f); acc.y = fmaxf(acc.y, 0.f);
    acc.z = fmaxf(acc.z, 0.f); acc.w = fmaxf(acc.w, 0.f);

    const __half2 o0 = __floats2half2_rn(acc.x, acc.y);
    const __half2 o1 = __floats2half2_rn(acc.z, acc.w);
    reinterpret_cast<uint2*>(A2 + (size_t)n * K2)[t] =
        make_uint2(*reinterpret_cast<const uint32_t*>(&o0),
                   *reinterpret_cast<const uint32_t*>(&o1));
}

// ---------------------------------------------------------------------------
// Fused aggregation 2: out = relu(segsum(s2[src]*w) + b2), fp32 out.
// One block (64 thr) per node; thread t owns cols [4t, 4t+4). s2 is fp16.
// ---------------------------------------------------------------------------
__global__ __launch_bounds__(64) void agg2_k(const __half* __restrict__ s2,
                                             const float* __restrict__ b2,
                                             float* __restrict__ out)
{
    const int n = blockIdx.x;
    const int t = threadIdx.x;
    const int beg = __ldg(&g_off[n]);
    const int end = __ldg(&g_off[n + 1]);

    float4 acc = __ldg(reinterpret_cast<const float4*>(b2) + t);
    for (int j = beg; j < end; j++) {
        const int   sr = __ldg(&g_esrc[j]);
        const float w  = __ldg(&g_ew2[j]);
        const uint2 pv = __ldg(reinterpret_cast<const uint2*>(s2 + (size_t)sr * D_LAT) + t);
        const __half2 h0 = *reinterpret_cast<const __half2*>(&pv.x);
        const __half2 h1 = *reinterpret_cast<const __half2*>(&pv.y);
        const float2 f0 = __half22float2(h0);
        const float2 f1 = __half22float2(h1);
        acc.x = fmaf(w, f0.x, acc.x);
        acc.y = fmaf(w, f0.y, acc.y);
        acc.z = fmaf(w, f1.x, acc.z);
        acc.w = fmaf(w, f1.y, acc.w);
    }
    acc.x = fmaxf(acc.x, 0.f); acc.y = fmaxf(acc.y, 0.f);
    acc.z = fmaxf(acc.z, 0.f); acc.w = fmaxf(acc.w, 0.f);
    reinterpret_cast<float4*>(out + (size_t)n * D_LAT)[t] = acc;
}

// ---------------------------------------------------------------------------
// Launch
// ---------------------------------------------------------------------------
extern "C" void kernel_launch(void* const* d_in, const int* in_sizes, int n_in,
                              void* d_out, int out_size)
{
    const float* x  = (const float*)d_in[0];   // [50000, 1024]
    const int*   ei = (const int*)d_in[1];     // [2, 400000]
    const float* ew = (const float*)d_in[2];   // [400000]
    const float* W1 = (const float*)d_in[3];   // [1024, 512]
    const float* b1 = (const float*)d_in[4];   // [512]
    const float* W2 = (const float*)d_in[5];   // [512, 256]
    const float* b2 = (const float*)d_in[6];   // [256]
    float* out = (float*)d_out;                // [50000, 256]

    static bool attr_set = false;
    if (!attr_set) {
        cudaFuncSetAttribute(gemm_mma_k, cudaFuncAttributeMaxDynamicSharedMemorySize,
                             GEMM_SMEM);
        attr_set = true;
    }

    __half *A1, *B1, *A2, *B2, *s_buf;
    cudaGetSymbolAddress((void**)&A1, g_A1);
    cudaGetSymbolAddress((void**)&B1, g_B1);
    cudaGetSymbolAddress((void**)&A2, g_A2);
    cudaGetSymbolAddress((void**)&B2, g_B2);
    cudaGetSymbolAddress((void**)&s_buf, g_s);

    const int* src = ei;
    const int* dst = ei + NE;
    const int nMt = NNP / 128;   // 391

    // Weight converts (tiny)
    split_w_k<<<dim3((D_IN  + 255) / 256, D_HID), 256>>>(W1, B1, D_IN,  D_HID);
    split_w_k<<<dim3((D_HID + 255) / 256, D_LAT), 256>>>(W2, B2, D_HID, D_LAT);

    // Input convert
    {
        unsigned total4 = (unsigned)NN * (D_IN / 4);
        split_a_k<<<(total4 + 255) / 256, 256>>>((const float4*)x, A1, total4);
    }

    // CSR build
    zero_deg_k<<<(NN + 255) / 256, 256>>>();
    hist_k<<<(NE + 255) / 256, 256>>>(dst);
    scan_k<<<1, SCAN_T>>>();
    fill_k<<<(NE + 255) / 256, 256>>>(src, dst, ew);

    // ---- Layer 1 ----
    gemm_mma_k<<<dim3(D_HID / 128, nMt), 256, GEMM_SMEM>>>(A1, B1, s_buf, K1, D_HID);
    agg1_k<<<NN, 128>>>(s_buf, b1, A2);   // fused: agg + b1 + relu + fp16

    // ---- Layer 2 ----
    gemm_mma_k<<<dim3(D_LAT / 128, nMt), 256, GEMM_SMEM>>>(A2, B2, s_buf, K2, D_LAT);
    agg2_k<<<NN, 64>>>(s_buf, b2, out);   // fused: agg + b2 + relu
}